// round 11
// baseline (speedup 1.0000x reference)
#include <cuda_runtime.h>
#include <cuda_fp16.h>
#include <cstdint>

#define CIN   256
#define COUT  256
#define HWD   64
#define NB    32
#define NPIX  4096
#define KTOT  2304            // 9 * 256
#define NSTAGE 36             // K chunks of 64

#define XROW  272             // padded row bytes for x tile [k64][pix128] fp16
#define WROW  144             // padded row bytes for w tile [co128][k64] fp16
#define X_SZ  (64 * XROW)     // 17408
#define W_SZ  (128 * WROW)    // 18432
#define ST_SZ (X_SZ + W_SZ)   // 35840
#define NRING 3
#define SMEM_BYTES (NRING * ST_SZ)   // 107520 per CTA (2 CTAs/SM)

// ---------------- device scratch ---------------------------------------------
__device__ float g_wsq[COUT * CIN];
__device__ float g_wt[(size_t)COUT * KTOT];                // w fp32, K-major per co
__device__ __half g_wh[(size_t)NB * COUT * KTOT];          // modulated w fp16, K-major
__device__ __half g_xh[(size_t)3 * NB * CIN * NPIX];       // x fp16, 3 dc-shifted copies

// ---------------- helpers -----------------------------------------------------
__device__ __forceinline__ uint32_t smem_u32(const void* p) {
    uint32_t a;
    asm("{ .reg .u64 t; cvta.to.shared.u64 t, %1; cvt.u32.u64 %0, t; }" : "=r"(a) : "l"(p));
    return a;
}
__device__ __forceinline__ void cp16(uint32_t dst, const void* src) {
    asm volatile("cp.async.cg.shared.global [%0], [%1], 16;" :: "r"(dst), "l"(src));
}
__device__ __forceinline__ void cp16z(uint32_t dst, const void* src, uint32_t nbytes) {
    asm volatile("cp.async.cg.shared.global [%0], [%1], 16, %2;"
                 :: "r"(dst), "l"(src), "r"(nbytes));
}
__device__ __forceinline__ void cp_commit() { asm volatile("cp.async.commit_group;"); }
__device__ __forceinline__ void cp_wait1()  { asm volatile("cp.async.wait_group 1;"); }

__device__ __forceinline__ void ldsm4(uint32_t* r, uint32_t a) {
    asm volatile("ldmatrix.sync.aligned.m8n8.x4.shared.b16 {%0,%1,%2,%3}, [%4];"
                 : "=r"(r[0]), "=r"(r[1]), "=r"(r[2]), "=r"(r[3]) : "r"(a));
}
__device__ __forceinline__ void ldsm4t(uint32_t* r, uint32_t a) {
    asm volatile("ldmatrix.sync.aligned.m8n8.x4.trans.shared.b16 {%0,%1,%2,%3}, [%4];"
                 : "=r"(r[0]), "=r"(r[1]), "=r"(r[2]), "=r"(r[3]) : "r"(a));
}
__device__ __forceinline__ void mma16816(float* c, const uint32_t* a, const uint32_t* b) {
    asm volatile("mma.sync.aligned.m16n8k16.row.col.f32.f16.f16.f32 "
                 "{%0,%1,%2,%3}, {%4,%5,%6,%7}, {%8,%9}, {%0,%1,%2,%3};"
                 : "+f"(c[0]), "+f"(c[1]), "+f"(c[2]), "+f"(c[3])
                 : "r"(a[0]), "r"(a[1]), "r"(a[2]), "r"(a[3]), "r"(b[0]), "r"(b[1]));
}

// ---------------- prologue ----------------------------------------------------
// fused: per-co smem transpose -> g_wt (K-major) + g_wsq
__global__ void k_wtsq(const float* __restrict__ w) {   // <<<256, 256>>>
    __shared__ float ws[KTOT];
    const int co = blockIdx.x, t = threadIdx.x;
    const float* wc = w + (size_t)co * KTOT;
#pragma unroll
    for (int i = 0; i < 9; i++) ws[t + i * 256] = wc[t + i * 256];
    __syncthreads();
    float s = 0.f;
#pragma unroll
    for (int k = 0; k < 9; k++) { float v = ws[t * 9 + k]; s += v * v; }
    g_wsq[co * CIN + t] = s;
    float* o = g_wt + (size_t)co * KTOT;
#pragma unroll
    for (int i = 0; i < 9; i++) {
        int idx = t + i * 256;            // kp*256 + ci
        o[idx] = ws[(idx & 255) * 9 + (idx >> 8)];
    }
}

// fused demod + modulate + fp16 cast. block = one (b, co) pair, 128 threads.
__global__ void k_wmod(const float* __restrict__ y) {   // <<<NB*COUT, 128>>>
    const int bc = blockIdx.x;
    const int co = bc & 255, b = bc >> 8;
    const int t  = threadIdx.x;
    const int ci = t * 2;

    float2 yv = *(const float2*)&y[b * CIN + ci];
    const float ym0 = yv.x + 1.f, ym1 = yv.y + 1.f;
    float2 wq = *(const float2*)&g_wsq[co * CIN + ci];
    float v = wq.x * ym0 * ym0 + wq.y * ym1 * ym1;
#pragma unroll
    for (int o = 16; o; o >>= 1) v += __shfl_xor_sync(0xffffffffu, v, o);
    __shared__ float sr[4];
    if ((t & 31) == 0) sr[t >> 5] = v;
    __syncthreads();
    const float d = rsqrtf(sr[0] + sr[1] + sr[2] + sr[3] + 1e-8f);

    const float* wt = g_wt + (size_t)co * KTOT;
    __half* wh = g_wh + (size_t)bc * KTOT;
#pragma unroll
    for (int kp = 0; kp < 9; kp++) {
        float2 wv = *(const float2*)&wt[kp * 256 + ci];
        *(__half2*)(wh + kp * 256 + ci) =
            __floats2half2_rn(wv.x * ym0 * d, wv.y * ym1 * d);
    }
}

// x fp32 -> fp16, 3 column-shifted zero-padded copies. Thread: 4 pixels.
__global__ void k_xcvt(const float* __restrict__ x) {
    int idx = blockIdx.x * 256 + threadIdx.x;          // NB*CIN*1024 threads
    int plane = idx >> 10;                             // b*CIN + ci
    int p0    = (idx & 1023) * 4;
    int c0    = p0 & 63;
    const float* xp = x + (size_t)plane * NPIX + p0;
    float4 v = *(const float4*)xp;
    float xm  = (c0 > 0)  ? xp[-1] : 0.f;
    float xp4 = (c0 < 60) ? xp[4]  : 0.f;
    __half2 o[3][2];
    o[0][0] = __floats2half2_rn(xm,  v.x);  o[0][1] = __floats2half2_rn(v.y, v.z);
    o[1][0] = __floats2half2_rn(v.x, v.y);  o[1][1] = __floats2half2_rn(v.z, v.w);
    o[2][0] = __floats2half2_rn(v.y, v.z);  o[2][1] = __floats2half2_rn(v.w, xp4);
#pragma unroll
    for (int d = 0; d < 3; d++) {
        __half* dst = g_xh + ((size_t)d * NB * CIN + plane) * NPIX + p0;
        *(__half2*)dst       = o[d][0];
        *(__half2*)(dst + 2) = o[d][1];
    }
}

// ---------------- main conv: HMMA fp16, 128pix x 128cout, 2 CTAs/SM -----------
__global__ void __launch_bounds__(256, 2) k_conv(const float* __restrict__ bias,
                                                 float* __restrict__ out) {
    extern __shared__ char smem[];
    const uint32_t sb0 = smem_u32(smem);
    const int t  = threadIdx.x;
    const int ln = t & 31;
    const int wp = t >> 5;
    const int wm = wp & 1;          // pixel half (64)
    const int wn = wp >> 1;         // cout 32-group (of 128)
    const int b  = blockIdx.z;
    const int co0 = blockIdx.y * 128;
    const int n0 = blockIdx.x * 128;
    const int r0 = blockIdx.x * 2;  // first image row of this tile

    const __half* gwh = g_wh + ((size_t)b * COUT + co0) * KTOT;

    const uint32_t a_lane = (uint32_t)(((ln & 7) + ((ln >> 4) & 1) * 8) * XROW
                                       + (wm * 64 + ((ln >> 3) & 1) * 8) * 2);
    const uint32_t b_lane = (uint32_t)(((ln & 7) + ((ln >> 4) & 1) * 8) * WROW
                                       + ((ln >> 3) & 1) * 16);

    float acc[4][4][4];
#pragma unroll
    for (int i = 0; i < 4; i++)
#pragma unroll
        for (int j = 0; j < 4; j++)
#pragma unroll
            for (int k = 0; k < 4; k++) acc[i][j][k] = 0.f;

    uint32_t Af[16], Bf[8];

    // ---- stage loader: X (4 chunks/thread) + W (4 chunks/thread) -------------
    auto load_stage = [&](int cs) {
        const int kp  = cs >> 2;                 // 0..8
        const int cic = (cs & 3) * 64;
        const int dr  = kp / 3 - 1;
        const int dv  = kp % 3;                  // dc + 1
        const uint32_t sbase = sb0 + (cs % NRING) * ST_SZ;
        const __half* xplane = g_xh + ((size_t)dv * NB + b) * CIN * NPIX;
#pragma unroll
        for (int j = 0; j < 4; j++) {
            const int chunk = j * 256 + t;       // 0..1023
            const int ci  = chunk >> 4;
            const int ch  = chunk & 15;
            const int gr  = r0 + (ch >> 3) + dr;
            const bool ok = (unsigned)gr < HWD;
            const __half* src = xplane + (size_t)(cic + ci) * NPIX
                                + (ok ? gr : 0) * HWD + (ch & 7) * 8;
            cp16z(sbase + ci * XROW + ch * 16, src, ok ? 16u : 0u);
        }
        const __half* wbase = gwh + kp * 256 + cic;
        const uint32_t wdst = sbase + X_SZ;
#pragma unroll
        for (int q = 0; q < 4; q++) {
            const int chunk = q * 256 + t;       // 0..1023
            const int row = chunk >> 3;          // 0..127 co
            const int u   = chunk & 7;
            cp16(wdst + row * WROW + u * 16, wbase + (size_t)row * KTOT + u * 8);
        }
    };

    // ---- prime ----
    load_stage(0); cp_commit();
    load_stage(1); cp_commit();
    cp_wait1();
    __syncthreads();

#pragma unroll 1
    for (int c = 0; c < NSTAGE; c++) {
        const uint32_t xs = sb0 + (c % NRING) * ST_SZ;
        const uint32_t ws = xs + X_SZ;
        if (c + 2 < NSTAGE) load_stage(c + 2);
        cp_commit();

#pragma unroll
        for (int sl = 0; sl < 4; sl++) {
            const uint32_t ax = xs + a_lane + sl * 16 * XROW;
#pragma unroll
            for (int mt = 0; mt < 4; mt++) ldsm4t(&Af[mt * 4], ax + mt * 32);
            const uint32_t bw = ws + b_lane + wn * 32 * WROW + sl * 32;
            ldsm4(&Bf[0], bw);
            ldsm4(&Bf[4], bw + 16 * WROW);
#pragma unroll
            for (int mt = 0; mt < 4; mt++)
#pragma unroll
                for (int q = 0; q < 4; q++)
                    mma16816(acc[mt][q], &Af[mt * 4], &Bf[q * 2]);
        }

        cp_wait1();
        __syncthreads();
    }

    // ---- epilogue ----
#pragma unroll
    for (int q = 0; q < 4; q++) {
        const int cg = co0 + wn * 32 + (q >> 1) * 16 + (q & 1) * 8 + (ln & 3) * 2;
        const float b0 = __ldg(&bias[cg]);
        const float b1 = __ldg(&bias[cg + 1]);
#pragma unroll
        for (int mt = 0; mt < 4; mt++) {
            const int pix = n0 + wm * 64 + mt * 16 + (ln >> 2);
            float* o = out + ((size_t)b * COUT + cg) * NPIX + pix;
            const float* C = acc[mt][q];
            o[0]        = C[0] + b0;
            o[NPIX]     = C[1] + b1;
            o[8]        = C[2] + b0;
            o[NPIX + 8] = C[3] + b1;
        }
    }
}

// ---------------- launch ------------------------------------------------------
extern "C" void kernel_launch(void* const* d_in, const int* in_sizes, int n_in,
                              void* d_out, int out_size) {
    const float* x    = (const float*)d_in[0];
    const float* y    = (const float*)d_in[1];
    const float* w    = (const float*)d_in[2];
    const float* bias = (const float*)d_in[3];
    float* out        = (float*)d_out;

    cudaFuncSetAttribute(k_conv, cudaFuncAttributeMaxDynamicSharedMemorySize, SMEM_BYTES);

    k_wtsq<<<COUT, 256>>>(w);
    k_wmod<<<NB * COUT, 128>>>(y);
    k_xcvt<<<NB * CIN * 1024 / 256, 256>>>(x);
    k_conv<<<dim3(NPIX / 128, 2, NB), 256, SMEM_BYTES>>>(bias, out);
}

// round 12
// speedup vs baseline: 1.2780x; 1.2780x over previous
#include <cuda_runtime.h>
#include <cuda_fp16.h>
#include <cstdint>

#define CIN   256
#define COUT  256
#define HWD   64
#define NB    32
#define NPIX  4096
#define KTOT  2304            // 9 * 256
#define NSTAGE 36             // K chunks of 64

#define XROW  272             // padded row bytes for x tile [k64][pix128] fp16
#define WROW  144             // padded row bytes for w tile [co][k64] fp16
#define X_SZ  (64 * XROW)     // 17408
#define W_SZ  (256 * WROW)    // 36864
#define ST_SZ (X_SZ + W_SZ)   // 54272
#define NRING 3
#define SMEM_BYTES (NRING * ST_SZ)   // 162816

// ---------------- device scratch ---------------------------------------------
__device__ float g_wsq[COUT * CIN];
__device__ float g_wt[(size_t)COUT * KTOT];                // w fp32, K-major per co
__device__ __half g_wh[(size_t)NB * COUT * KTOT];          // modulated w fp16, K-major
__device__ __half g_xh[(size_t)3 * NB * CIN * NPIX];       // x fp16, 3 dc-shifted copies

// ---------------- helpers -----------------------------------------------------
__device__ __forceinline__ uint32_t smem_u32(const void* p) {
    uint32_t a;
    asm("{ .reg .u64 t; cvta.to.shared.u64 t, %1; cvt.u32.u64 %0, t; }" : "=r"(a) : "l"(p));
    return a;
}
__device__ __forceinline__ void cp16(uint32_t dst, const void* src) {
    asm volatile("cp.async.cg.shared.global [%0], [%1], 16;" :: "r"(dst), "l"(src));
}
__device__ __forceinline__ void cp16z(uint32_t dst, const void* src, uint32_t nbytes) {
    asm volatile("cp.async.cg.shared.global [%0], [%1], 16, %2;"
                 :: "r"(dst), "l"(src), "r"(nbytes));
}
__device__ __forceinline__ void cp_commit() { asm volatile("cp.async.commit_group;"); }
__device__ __forceinline__ void cp_wait1()  { asm volatile("cp.async.wait_group 1;"); }

__device__ __forceinline__ void ldsm4(uint32_t* r, uint32_t a) {
    asm volatile("ldmatrix.sync.aligned.m8n8.x4.shared.b16 {%0,%1,%2,%3}, [%4];"
                 : "=r"(r[0]), "=r"(r[1]), "=r"(r[2]), "=r"(r[3]) : "r"(a));
}
__device__ __forceinline__ void ldsm4t(uint32_t* r, uint32_t a) {
    asm volatile("ldmatrix.sync.aligned.m8n8.x4.trans.shared.b16 {%0,%1,%2,%3}, [%4];"
                 : "=r"(r[0]), "=r"(r[1]), "=r"(r[2]), "=r"(r[3]) : "r"(a));
}
__device__ __forceinline__ void mma16816(float* c, const uint32_t* a, const uint32_t* b) {
    asm volatile("mma.sync.aligned.m16n8k16.row.col.f32.f16.f16.f32 "
                 "{%0,%1,%2,%3}, {%4,%5,%6,%7}, {%8,%9}, {%0,%1,%2,%3};"
                 : "+f"(c[0]), "+f"(c[1]), "+f"(c[2]), "+f"(c[3])
                 : "r"(a[0]), "r"(a[1]), "r"(a[2]), "r"(a[3]), "r"(b[0]), "r"(b[1]));
}

// ---------------- prologue ----------------------------------------------------
// fused: blocks [0, 32768) convert x; blocks [32768, 33024) transpose w + wsq.
__global__ void k_pre(const float* __restrict__ x, const float* __restrict__ w) {
    if (blockIdx.x < 32768) {
        // ---- x fp32 -> fp16, 3 column-shifted zero-padded copies --------------
        int idx = blockIdx.x * 256 + threadIdx.x;
        int plane = idx >> 10;                             // b*CIN + ci
        int p0    = (idx & 1023) * 4;
        int c0    = p0 & 63;
        const float* xp = x + (size_t)plane * NPIX + p0;
        float4 v = *(const float4*)xp;
        float xm  = (c0 > 0)  ? xp[-1] : 0.f;
        float xp4 = (c0 < 60) ? xp[4]  : 0.f;
        __half2 o[3][2];
        o[0][0] = __floats2half2_rn(xm,  v.x);  o[0][1] = __floats2half2_rn(v.y, v.z);
        o[1][0] = __floats2half2_rn(v.x, v.y);  o[1][1] = __floats2half2_rn(v.z, v.w);
        o[2][0] = __floats2half2_rn(v.y, v.z);  o[2][1] = __floats2half2_rn(v.w, xp4);
#pragma unroll
        for (int d = 0; d < 3; d++) {
            __half* dst = g_xh + ((size_t)d * NB * CIN + plane) * NPIX + p0;
            *(__half2*)dst       = o[d][0];
            *(__half2*)(dst + 2) = o[d][1];
        }
    } else {
        // ---- per-co smem transpose -> g_wt (K-major) + g_wsq -----------------
        __shared__ float ws[KTOT];
        const int co = blockIdx.x - 32768, t = threadIdx.x;
        const float* wc = w + (size_t)co * KTOT;
#pragma unroll
        for (int i = 0; i < 9; i++) ws[t + i * 256] = wc[t + i * 256];
        __syncthreads();
        float s = 0.f;
#pragma unroll
        for (int k = 0; k < 9; k++) { float v = ws[t * 9 + k]; s += v * v; }
        g_wsq[co * CIN + t] = s;
        float* o = g_wt + (size_t)co * KTOT;
#pragma unroll
        for (int i = 0; i < 9; i++) {
            int idx = t + i * 256;            // kp*256 + ci
            o[idx] = ws[(idx & 255) * 9 + (idx >> 8)];
        }
    }
}

// fused demod + modulate + fp16 cast. block = one (b, co) pair, 128 threads.
__global__ void k_wmod(const float* __restrict__ y) {   // <<<NB*COUT, 128>>>
    const int bc = blockIdx.x;
    const int co = bc & 255, b = bc >> 8;
    const int t  = threadIdx.x;
    const int ci = t * 2;

    float2 yv = *(const float2*)&y[b * CIN + ci];
    const float ym0 = yv.x + 1.f, ym1 = yv.y + 1.f;
    float2 wq = *(const float2*)&g_wsq[co * CIN + ci];
    float v = wq.x * ym0 * ym0 + wq.y * ym1 * ym1;
#pragma unroll
    for (int o = 16; o; o >>= 1) v += __shfl_xor_sync(0xffffffffu, v, o);
    __shared__ float sr[4];
    if ((t & 31) == 0) sr[t >> 5] = v;
    __syncthreads();
    const float d = rsqrtf(sr[0] + sr[1] + sr[2] + sr[3] + 1e-8f);

    const float* wt = g_wt + (size_t)co * KTOT;
    __half* wh = g_wh + (size_t)bc * KTOT;
#pragma unroll
    for (int kp = 0; kp < 9; kp++) {
        float2 wv = *(const float2*)&wt[kp * 256 + ci];
        *(__half2*)(wh + kp * 256 + ci) =
            __floats2half2_rn(wv.x * ym0 * d, wv.y * ym1 * d);
    }
}

// ---------------- main conv: HMMA fp16 implicit GEMM, K64 stages --------------
// CTA: 128 pixels (M) x 256 cout (N), K = 2304, ring-3 cp.async, frag dbl-buf.
__global__ void __launch_bounds__(256, 1) k_conv(const float* __restrict__ bias,
                                                 float* __restrict__ out) {
    extern __shared__ char smem[];
    const uint32_t sb0 = smem_u32(smem);
    const int t  = threadIdx.x;
    const int ln = t & 31;
    const int wp = t >> 5;
    const int wm = wp & 1;          // pixel half (64)
    const int wn = wp >> 1;         // cout quarter (64)
    const int b  = blockIdx.y;
    const int n0 = blockIdx.x * 128;
    const int r0 = blockIdx.x * 2;  // first image row of this tile

    const __half* gwh = g_wh + (size_t)b * COUT * KTOT;

    const uint32_t a_lane = (uint32_t)(((ln & 7) + ((ln >> 4) & 1) * 8) * XROW
                                       + (wm * 64 + ((ln >> 3) & 1) * 8) * 2);
    const uint32_t b_lane = (uint32_t)(((ln & 7) + ((ln >> 4) & 1) * 8) * WROW
                                       + ((ln >> 3) & 1) * 16);

    float acc[4][8][4];
#pragma unroll
    for (int i = 0; i < 4; i++)
#pragma unroll
        for (int j = 0; j < 8; j++)
#pragma unroll
            for (int k = 0; k < 4; k++) acc[i][j][k] = 0.f;

    uint32_t Af[2][16], Bf[2][16];

    // ---- stage loader: X (4 chunks/thread) + W (8 chunks/thread) -------------
    auto load_stage = [&](int cs) {
        const int kp  = cs >> 2;                 // 0..8
        const int cic = (cs & 3) * 64;
        const int dr  = kp / 3 - 1;
        const int dv  = kp % 3;                  // dc + 1
        const uint32_t sbase = sb0 + (cs % NRING) * ST_SZ;
        const __half* xplane = g_xh + ((size_t)dv * NB + b) * CIN * NPIX;
#pragma unroll
        for (int j = 0; j < 4; j++) {
            const int chunk = j * 256 + t;       // 0..1023
            const int ci  = chunk >> 4;
            const int ch  = chunk & 15;
            const int gr  = r0 + (ch >> 3) + dr;
            const bool ok = (unsigned)gr < HWD;
            const __half* src = xplane + (size_t)(cic + ci) * NPIX
                                + (ok ? gr : 0) * HWD + (ch & 7) * 8;
            cp16z(sbase + ci * XROW + ch * 16, src, ok ? 16u : 0u);
        }
        const __half* wbase = gwh + kp * 256 + cic;
        const uint32_t wdst = sbase + X_SZ;
#pragma unroll
        for (int q = 0; q < 8; q++) {
            const int chunk = q * 256 + t;       // 0..2047
            const int row = chunk >> 3;
            const int u   = chunk & 7;
            cp16(wdst + row * WROW + u * 16, wbase + (size_t)row * KTOT + u * 8);
        }
    };

    // ---- frag loader for k16 slice sl of the stage at (xs, ws) ---------------
    auto load_frags = [&](uint32_t xs, uint32_t ws, int sl, int pb) {
        const uint32_t ax = xs + a_lane + sl * 16 * XROW;
#pragma unroll
        for (int mt = 0; mt < 4; mt++) ldsm4t(&Af[pb][mt * 4], ax + mt * 32);
        const uint32_t bw = ws + b_lane + wn * 64 * WROW + sl * 32;
        ldsm4(&Bf[pb][0],  bw);
        ldsm4(&Bf[pb][4],  bw + 16 * WROW);
        ldsm4(&Bf[pb][8],  bw + 32 * WROW);
        ldsm4(&Bf[pb][12], bw + 48 * WROW);
    };
    auto compute = [&](int pb) {
#pragma unroll
        for (int h = 0; h < 2; h++)
#pragma unroll
            for (int mt = 0; mt < 4; mt++)
#pragma unroll
                for (int q = 0; q < 4; q++)
                    mma16816(acc[mt][h * 4 + q], &Af[pb][mt * 4], &Bf[pb][h * 8 + q * 2]);
    };

    // ---- prime ----
    load_stage(0); cp_commit();
    load_stage(1); cp_commit();
    cp_wait1();
    __syncthreads();
    load_frags(sb0, sb0 + X_SZ, 0, 0);

#pragma unroll 1
    for (int c = 0; c < NSTAGE; c++) {
        const uint32_t xs = sb0 + (c % NRING) * ST_SZ;
        const uint32_t ws = xs + X_SZ;
        if (c + 2 < NSTAGE) load_stage(c + 2);
        cp_commit();

#pragma unroll
        for (int sl = 0; sl < 4; sl++) {
            const int pb = sl & 1;
            if (sl < 3) load_frags(xs, ws, sl + 1, pb ^ 1);
            compute(pb);
        }

        cp_wait1();
        __syncthreads();
        if (c + 1 < NSTAGE) {
            const uint32_t nxs = sb0 + ((c + 1) % NRING) * ST_SZ;
            load_frags(nxs, nxs + X_SZ, 0, 0);
        }
    }

    // ---- epilogue ----
#pragma unroll
    for (int h = 0; h < 2; h++)
#pragma unroll
        for (int q = 0; q < 4; q++) {
            const int co0 = wn * 64 + h * 32 + (q >> 1) * 16 + (q & 1) * 8 + (ln & 3) * 2;
            const float b0 = __ldg(&bias[co0]);
            const float b1 = __ldg(&bias[co0 + 1]);
#pragma unroll
            for (int mt = 0; mt < 4; mt++) {
                const int pix = n0 + wm * 64 + mt * 16 + (ln >> 2);
                float* o = out + ((size_t)b * COUT + co0) * NPIX + pix;
                const float* C = acc[mt][h * 4 + q];
                o[0]        = C[0] + b0;
                o[NPIX]     = C[1] + b1;
                o[8]        = C[2] + b0;
                o[NPIX + 8] = C[3] + b1;
            }
        }
}

// ---------------- launch ------------------------------------------------------
extern "C" void kernel_launch(void* const* d_in, const int* in_sizes, int n_in,
                              void* d_out, int out_size) {
    const float* x    = (const float*)d_in[0];
    const float* y    = (const float*)d_in[1];
    const float* w    = (const float*)d_in[2];
    const float* bias = (const float*)d_in[3];
    float* out        = (float*)d_out;

    cudaFuncSetAttribute(k_conv, cudaFuncAttributeMaxDynamicSharedMemorySize, SMEM_BYTES);

    k_pre<<<32768 + 256, 256>>>(x, w);
    k_wmod<<<NB * COUT, 128>>>(y);
    k_conv<<<dim3(NPIX / 128, NB), 256, SMEM_BYTES>>>(bias, out);
}